// round 10
// baseline (speedup 1.0000x reference)
#include <cuda_runtime.h>
#include <cuda_bf16.h>
#include <cstdint>

#define EPSF 1e-8f
constexpr int B  = 8;
constexpr int Nn = 2048;
constexpr int H  = 128;
constexpr int SPL2 = 8;          // split-K for C = N^T H (MMA version)

// Scratch (device globals: allocation-free rule)
__device__ float g_agg1[B * Nn * H];
__device__ float g_agg2[B * Nn * H];
__device__ float g_part[2 * B * SPL2 * H * H];
// bf16 split planes of normalized n and raw h: [which][b][n][k]
__device__ __nv_bfloat16 g_nbhi[2 * B * Nn * H];
__device__ __nv_bfloat16 g_nblo[2 * B * Nn * H];
__device__ __nv_bfloat16 g_hbhi[2 * B * Nn * H];
__device__ __nv_bfloat16 g_hblo[2 * B * Nn * H];
// Ct[h,k] = C[k,h] split planes: [w][b][h][k]
__device__ __nv_bfloat16 g_Cthi[2 * B * H * H];
__device__ __nv_bfloat16 g_Ctlo[2 * B * H * H];
__device__ __nv_bfloat16 g_w2hi[H * H];
__device__ __nv_bfloat16 g_w2lo[H * H];

// ======================= warp MMA helpers (base ISA, sm_80+) =================
__device__ __forceinline__ uint32_t smem_to_u32(const void* p) {
    uint32_t a;
    asm("{ .reg .u64 t; cvta.to.shared.u64 t, %1; cvt.u32.u64 %0, t; }" : "=r"(a) : "l"(p));
    return a;
}
__device__ __forceinline__ void ldsm4(uint32_t* r, uint32_t addr) {
    asm volatile("ldmatrix.sync.aligned.m8n8.x4.shared.b16 {%0,%1,%2,%3}, [%4];"
                 : "=r"(r[0]), "=r"(r[1]), "=r"(r[2]), "=r"(r[3]) : "r"(addr));
}
__device__ __forceinline__ void ldsm4t(uint32_t* r, uint32_t addr) {
    asm volatile("ldmatrix.sync.aligned.m8n8.x4.trans.shared.b16 {%0,%1,%2,%3}, [%4];"
                 : "=r"(r[0]), "=r"(r[1]), "=r"(r[2]), "=r"(r[3]) : "r"(addr));
}
__device__ __forceinline__ void mma_bf16(float* c, const uint32_t* a,
                                         uint32_t b0, uint32_t b1) {
    asm volatile("mma.sync.aligned.m16n8k16.row.col.f32.bf16.bf16.f32 "
                 "{%0,%1,%2,%3}, {%4,%5,%6,%7}, {%8,%9}, {%0,%1,%2,%3};"
                 : "+f"(c[0]), "+f"(c[1]), "+f"(c[2]), "+f"(c[3])
                 : "r"(a[0]), "r"(a[1]), "r"(a[2]), "r"(a[3]), "r"(b0), "r"(b1));
}
__device__ __forceinline__ uint32_t pack_bf2(float a, float b) {
    __nv_bfloat162 t = __floats2bfloat162_rn(a, b);
    return *reinterpret_cast<uint32_t*>(&t);
}
__device__ __forceinline__ void split4(const float* v, uint2& phi, uint2& plo) {
    float hi[4], lo[4];
#pragma unroll
    for (int i = 0; i < 4; i++) {
        __nv_bfloat16 h = __float2bfloat16(v[i]);
        hi[i] = __bfloat162float(h);
        lo[i] = v[i] - hi[i];
    }
    phi = make_uint2(pack_bf2(hi[0], hi[1]), pack_bf2(hi[2], hi[3]));
    plo = make_uint2(pack_bf2(lo[0], lo[1]), pack_bf2(lo[2], lo[3]));
}

constexpr int AROW  = 272;                 // 136 bf16 per smem row
constexpr int PLANE = 128 * AROW;          // 34816 bytes
constexpr int MM_SMEM = 4 * PLANE;         // 139264

// ---------------------------------------------------------------------------
// K1: row-normalize -> bf16 hi/lo planes of n, plus split planes of raw h.
// ---------------------------------------------------------------------------
__global__ void normalize_kernel(const float* __restrict__ h1,
                                 const float* __restrict__ h2) {
    int warp = (blockIdx.x * blockDim.x + threadIdx.x) >> 5;
    int lane = threadIdx.x & 31;
    int which = (warp < B * Nn) ? 0 : 1;
    int row = warp - which * B * Nn;
    const float* src = which ? h2 : h1;

    float4 v = ((const float4*)(src + (size_t)row * H))[lane];
    float ss = v.x * v.x + v.y * v.y + v.z * v.z + v.w * v.w;
#pragma unroll
    for (int o = 16; o; o >>= 1) ss += __shfl_xor_sync(0xffffffffu, ss, o);
    float inv = 1.0f / fmaxf(sqrtf(ss), EPSF);

    size_t off = ((size_t)which * B * Nn + row) * H + lane * 4;
    float r4[4] = {v.x * inv, v.y * inv, v.z * inv, v.w * inv};
    uint2 phi, plo;
    split4(r4, phi, plo);
    *(uint2*)&g_nbhi[off] = phi;
    *(uint2*)&g_nblo[off] = plo;

    float h4[4] = {v.x, v.y, v.z, v.w};
    split4(h4, phi, plo);
    *(uint2*)&g_hbhi[off] = phi;
    *(uint2*)&g_hblo[off] = plo;
}

// ---------------------------------------------------------------------------
// K2a: Ct partials via mma.sync with transposed fragments.
//   Ct[h,k] = sum_n H[n,h] * N[n,k]   (w=0: which=1 (h2,n2); w=1: which=0)
// CTA (s, b, w): contraction rows s*256..s*256+255, full 128x128 output.
// Both fragments loaded with ldmatrix.trans from [n][.]-major planes.
// ---------------------------------------------------------------------------
__global__ void __launch_bounds__(256, 1) cmat_mma_kernel() {
    extern __shared__ char smem[];
    uint32_t sb = smem_to_u32(smem);
    const int tid = threadIdx.x, wid = tid >> 5, lane = tid & 31;
    const int s = blockIdx.x, b = blockIdx.y, w = blockIdx.z;
    const int which = 1 - w;

    size_t base = ((size_t)which * B * Nn + (size_t)b * Nn + (size_t)s * 256) * H;
    const __nv_bfloat16* Hh = g_hbhi + base;
    const __nv_bfloat16* Hl = g_hblo + base;
    const __nv_bfloat16* Nh = g_nbhi + base;
    const __nv_bfloat16* Nl = g_nblo + base;

    const int wm = (wid >> 1) * 32, wn = (wid & 1) * 64;   // wm: h rows, wn: k cols
    // trans ldmatrix address components
    const int cA = (lane & 7) + ((lane >> 4) << 3);        // A: contraction row
    const int mA = ((lane >> 3) & 1) * 8;                  // A: h col offset
    const int nB = (lane & 7) + ((lane >> 3) & 1) * 8;     // B: contraction row
    const int kB = (lane >> 4) * 8;                        // B: k col offset

    float acc[2][8][4];
#pragma unroll
    for (int mi = 0; mi < 2; mi++)
#pragma unroll
        for (int j = 0; j < 8; j++)
#pragma unroll
            for (int q = 0; q < 4; q++) acc[mi][j][q] = 0.0f;

    for (int chunk = 0; chunk < 2; ++chunk) {
        __syncthreads();
        const size_t roff = (size_t)chunk * 128 * H;
        for (int i = tid; i < 128 * 16; i += 256) {
            int r = i >> 4, ck = i & 15;
            uint32_t d = (uint32_t)r * AROW + (uint32_t)ck * 16;
            *(uint4*)(smem + d)             = *(const uint4*)(Hh + roff + r * H + ck * 8);
            *(uint4*)(smem + PLANE + d)     = *(const uint4*)(Hl + roff + r * H + ck * 8);
            *(uint4*)(smem + 2 * PLANE + d) = *(const uint4*)(Nh + roff + r * H + ck * 8);
            *(uint4*)(smem + 3 * PLANE + d) = *(const uint4*)(Nl + roff + r * H + ck * 8);
        }
        __syncthreads();

#pragma unroll 2
        for (int ks = 0; ks < 8; ks++) {
            const int c0 = ks * 16;
            uint32_t ah[2][4], al[2][4];
#pragma unroll
            for (int mi = 0; mi < 2; mi++) {
                uint32_t addr = sb + (uint32_t)(c0 + cA) * AROW +
                                (uint32_t)(wm + mi * 16 + mA) * 2;
                ldsm4t(ah[mi], addr);
                ldsm4t(al[mi], addr + PLANE);
            }
            uint32_t bh[4][4], bl[4][4];
#pragma unroll
            for (int jp = 0; jp < 4; jp++) {
                uint32_t addr = sb + 2 * PLANE + (uint32_t)(c0 + nB) * AROW +
                                (uint32_t)(wn + jp * 16 + kB) * 2;
                ldsm4t(bh[jp], addr);
                ldsm4t(bl[jp], addr + PLANE);
            }
#pragma unroll
            for (int j = 0; j < 8; j++) {
                uint32_t b0h = bh[j >> 1][(j & 1) * 2], b1h = bh[j >> 1][(j & 1) * 2 + 1];
                uint32_t b0l = bl[j >> 1][(j & 1) * 2], b1l = bl[j >> 1][(j & 1) * 2 + 1];
#pragma unroll
                for (int mi = 0; mi < 2; mi++) {
                    mma_bf16(acc[mi][j], ah[mi], b0h, b1h);   // hi*hi
                    mma_bf16(acc[mi][j], al[mi], b0h, b1h);   // lo*hi
                    mma_bf16(acc[mi][j], ah[mi], b0l, b1l);   // hi*lo
                }
            }
        }
    }

    float* P = g_part + ((size_t)(w * B + b) * SPL2 + s) * (H * H);
    const int g = lane >> 2, tc = (lane & 3) * 2;
#pragma unroll
    for (int mi = 0; mi < 2; mi++)
#pragma unroll
        for (int j = 0; j < 8; j++) {
            int row = wm + mi * 16 + g, col = wn + j * 8 + tc;
            *(float2*)&P[(size_t)row * H + col]       = make_float2(acc[mi][j][0], acc[mi][j][1]);
            *(float2*)&P[(size_t)(row + 8) * H + col] = make_float2(acc[mi][j][2], acc[mi][j][3]);
        }
}

// K2b: coalesced reduce of SPL2 partials -> Ct split planes (no transpose)
__global__ void cmat_reduce_kernel() {
    const int b = blockIdx.y, w = blockIdx.z;
    const int u = blockIdx.x * 256 + threadIdx.x;        // float4 unit, 4096 per (b,w)
    const float* P = g_part + (size_t)(w * B + b) * SPL2 * (H * H);
    float4 sum = make_float4(0.f, 0.f, 0.f, 0.f);
#pragma unroll
    for (int sp = 0; sp < SPL2; sp++) {
        float4 v = *(const float4*)&P[(size_t)sp * (H * H) + u * 4];
        sum.x += v.x; sum.y += v.y; sum.z += v.z; sum.w += v.w;
    }
    float v4[4] = {sum.x, sum.y, sum.z, sum.w};
    uint2 phi, plo;
    split4(v4, phi, plo);
    size_t off = (size_t)(w * B + b) * (H * H) + (size_t)u * 4;
    *(uint2*)&g_Cthi[off] = phi;
    *(uint2*)&g_Ctlo[off] = plo;
}

// ---------------------------------------------------------------------------
// K3: apply via mma.sync — agg[r,h] = sum_k N[r,k] * Ct[h,k]
// ---------------------------------------------------------------------------
__global__ void __launch_bounds__(256, 1) apply_mma_kernel() {
    extern __shared__ char smem[];
    uint32_t sb = smem_to_u32(smem);
    const int tid = threadIdx.x, wid = tid >> 5, lane = tid & 31;
    const int mt = blockIdx.x, b = blockIdx.y, dir = blockIdx.z;

    size_t abase = ((size_t)dir * B * Nn + (size_t)b * Nn + (size_t)mt * 128) * H;
    const __nv_bfloat16* Ahg = g_nbhi + abase;
    const __nv_bfloat16* Alg = g_nblo + abase;
    const __nv_bfloat16* Bhg = g_Cthi + (size_t)(dir * B + b) * (H * H);
    const __nv_bfloat16* Blg = g_Ctlo + (size_t)(dir * B + b) * (H * H);

    for (int i = tid; i < 128 * 16; i += 256) {
        int r = i >> 4, ck = i & 15;
        uint32_t d = (uint32_t)r * AROW + (uint32_t)ck * 16;
        *(uint4*)(smem + d)             = *(const uint4*)(Ahg + r * H + ck * 8);
        *(uint4*)(smem + PLANE + d)     = *(const uint4*)(Alg + r * H + ck * 8);
        *(uint4*)(smem + 2 * PLANE + d) = *(const uint4*)(Bhg + r * H + ck * 8);
        *(uint4*)(smem + 3 * PLANE + d) = *(const uint4*)(Blg + r * H + ck * 8);
    }
    __syncthreads();

    const int wm = (wid >> 1) * 32, wn = (wid & 1) * 64;
    const int lr = lane & 15;
    const uint32_t lc2 = (uint32_t)(lane >> 4) * 16;
    uint32_t aoff[2], boff[4];
#pragma unroll
    for (int mi = 0; mi < 2; mi++)
        aoff[mi] = sb + (uint32_t)(wm + mi * 16 + lr) * AROW + lc2;
#pragma unroll
    for (int jp = 0; jp < 4; jp++)
        boff[jp] = sb + 2 * PLANE + (uint32_t)(wn + jp * 16 + lr) * AROW + lc2;

    float acc[2][8][4];
#pragma unroll
    for (int mi = 0; mi < 2; mi++)
#pragma unroll
        for (int j = 0; j < 8; j++)
#pragma unroll
            for (int q = 0; q < 4; q++) acc[mi][j][q] = 0.0f;

#pragma unroll 2
    for (int ks = 0; ks < 8; ks++) {
        uint32_t kb = (uint32_t)ks * 32;
        uint32_t ah[2][4], al[2][4];
#pragma unroll
        for (int mi = 0; mi < 2; mi++) {
            ldsm4(ah[mi], aoff[mi] + kb);
            ldsm4(al[mi], aoff[mi] + PLANE + kb);
        }
        uint32_t bh[4][4], bl[4][4];
#pragma unroll
        for (int jp = 0; jp < 4; jp++) {
            ldsm4(bh[jp], boff[jp] + kb);
            ldsm4(bl[jp], boff[jp] + PLANE + kb);
        }
#pragma unroll
        for (int j = 0; j < 8; j++) {
            uint32_t b0h = bh[j >> 1][j & 1], b1h = bh[j >> 1][(j & 1) + 2];
            uint32_t b0l = bl[j >> 1][j & 1], b1l = bl[j >> 1][(j & 1) + 2];
#pragma unroll
            for (int mi = 0; mi < 2; mi++) {
                mma_bf16(acc[mi][j], ah[mi], b0h, b1h);
                mma_bf16(acc[mi][j], al[mi], b0h, b1h);
                mma_bf16(acc[mi][j], ah[mi], b0l, b1l);
            }
        }
    }

    float* D = (dir == 0 ? g_agg1 : g_agg2) + ((size_t)b * Nn + (size_t)mt * 128) * H;
    const int g = lane >> 2, tc = (lane & 3) * 2;
#pragma unroll
    for (int mi = 0; mi < 2; mi++)
#pragma unroll
        for (int j = 0; j < 8; j++) {
            int row = wm + mi * 16 + g, col = wn + j * 8 + tc;
            *(float2*)&D[(size_t)row * H + col]       = make_float2(acc[mi][j][0], acc[mi][j][1]);
            *(float2*)&D[(size_t)(row + 8) * H + col] = make_float2(acc[mi][j][2], acc[mi][j][3]);
        }
}

// ---------------------------------------------------------------------------
// K4a: W2 = w*w, split to bf16 hi/lo
// ---------------------------------------------------------------------------
__global__ void w2_prep_kernel(const float* __restrict__ w_m) {
    int u = blockIdx.x * 256 + threadIdx.x;
    float4 w = *(const float4*)&w_m[u * 4];
    float v[4] = {w.x * w.x, w.y * w.y, w.z * w.z, w.w * w.w};
    uint2 phi, plo;
    split4(v, phi, plo);
    *(uint2*)&g_w2hi[u * 4] = phi;
    *(uint2*)&g_w2lo[u * 4] = plo;
}

// ---------------------------------------------------------------------------
// K4b: fused fm (unchanged from round 8/9 winner)
// ---------------------------------------------------------------------------
constexpr int APL      = 64 * AROW;            // 17408
constexpr int FMF_BOFF = 6 * APL;              // 104448
constexpr int FMF_SMEM = FMF_BOFF + 2 * PLANE; // 174080

__global__ void __launch_bounds__(256, 1)
fm_fused_kernel(const float* __restrict__ h1, const float* __restrict__ h2,
                float* __restrict__ out) {
    extern __shared__ char smem[];
    uint32_t sb = smem_to_u32(smem);
    const int tid = threadIdx.x, wid = tid >> 5, lane = tid & 31;
    const int mt = blockIdx.x, b = blockIdx.y, dir = blockIdx.z;

    const float* X = (dir ? h2 : h1) + ((size_t)b * Nn + (size_t)mt * 64) * H;
    const float* Y = (dir ? g_agg2 : g_agg1) + ((size_t)b * Nn + (size_t)mt * 64) * H;

    for (int i = tid; i < 64 * 32; i += 256) {
        int r = i >> 5, c4 = (i & 31) << 2;
        float4 x = *(const float4*)&X[r * H + c4];
        float4 y = *(const float4*)&Y[r * H + c4];
        float ch[3][4] = {
            {x.x * y.x, x.y * y.y, x.z * y.z, x.w * y.w},
            {x.x * x.x, x.y * x.y, x.z * x.z, x.w * x.w},
            {y.x * y.x, y.y * y.y, y.z * y.z, y.w * y.w}};
        uint32_t d = (uint32_t)r * AROW + (uint32_t)c4 * 2;
#pragma unroll
        for (int c = 0; c < 3; c++) {
            uint2 phi, plo;
            split4(ch[c], phi, plo);
            *(uint2*)(smem + (c * 2 + 0) * APL + d) = phi;
            *(uint2*)(smem + (c * 2 + 1) * APL + d) = plo;
        }
    }
    for (int i = tid; i < 128 * 16; i += 256) {
        int r = i >> 4, ck = i & 15;
        uint32_t d = (uint32_t)r * AROW + (uint32_t)ck * 16;
        *(uint4*)(smem + FMF_BOFF + d)         = *(const uint4*)(g_w2hi + r * H + ck * 8);
        *(uint4*)(smem + FMF_BOFF + PLANE + d) = *(const uint4*)(g_w2lo + r * H + ck * 8);
    }
    __syncthreads();

    const int wm = (wid >> 1) * 16, wn = (wid & 1) * 64;
    const int lr = lane & 15;
    const uint32_t lc2 = (uint32_t)(lane >> 4) * 16;
    uint32_t aoff[3][2], boff[4][2];
#pragma unroll
    for (int c = 0; c < 3; c++)
#pragma unroll
        for (int hl = 0; hl < 2; hl++)
            aoff[c][hl] = sb + (uint32_t)(c * 2 + hl) * APL + (uint32_t)(wm + lr) * AROW + lc2;
#pragma unroll
    for (int jp = 0; jp < 4; jp++)
#pragma unroll
        for (int hl = 0; hl < 2; hl++)
            boff[jp][hl] = sb + FMF_BOFF + (uint32_t)hl * PLANE +
                           (uint32_t)(wn + jp * 16 + lr) * AROW + lc2;

    float acc[3][8][4];
#pragma unroll
    for (int c = 0; c < 3; c++)
#pragma unroll
        for (int j = 0; j < 8; j++)
#pragma unroll
            for (int q = 0; q < 4; q++) acc[c][j][q] = 0.0f;

    for (int ks = 0; ks < 8; ks++) {
        uint32_t kb = (uint32_t)ks * 32;
        uint32_t ah[3][4], al[3][4];
#pragma unroll
        for (int c = 0; c < 3; c++) {
            ldsm4(ah[c], aoff[c][0] + kb);
            ldsm4(al[c], aoff[c][1] + kb);
        }
        uint32_t bh[4][4], bl[4][4];
#pragma unroll
        for (int jp = 0; jp < 4; jp++) {
            ldsm4(bh[jp], boff[jp][0] + kb);
            ldsm4(bl[jp], boff[jp][1] + kb);
        }
#pragma unroll
        for (int j = 0; j < 8; j++) {
            uint32_t b0h = bh[j >> 1][j & 1], b1h = bh[j >> 1][(j & 1) + 2];
            uint32_t b0l = bl[j >> 1][j & 1], b1l = bl[j >> 1][(j & 1) + 2];
#pragma unroll
            for (int c = 0; c < 3; c++) {
                mma_bf16(acc[c][j], ah[c], b0h, b1h);
                mma_bf16(acc[c][j], al[c], b0h, b1h);
                mma_bf16(acc[c][j], ah[c], b0l, b1l);
            }
        }
    }

    float* O = out + ((size_t)(dir * B + b) * Nn + (size_t)mt * 64) * H;
    const int g = lane >> 2, tc = (lane & 3) * 2;
#pragma unroll
    for (int j = 0; j < 8; j++) {
        int col = wn + j * 8 + tc;
#pragma unroll
        for (int half = 0; half < 2; half++) {
            int row = wm + half * 8 + g;
            float n0 = acc[0][j][half * 2], n1 = acc[0][j][half * 2 + 1];
            float x0 = acc[1][j][half * 2], x1 = acc[1][j][half * 2 + 1];
            float y0 = acc[2][j][half * 2], y1 = acc[2][j][half * 2 + 1];
            float2 o;
            o.x = n0 / (fmaxf(sqrtf(x0), EPSF) * fmaxf(sqrtf(y0), EPSF));
            o.y = n1 / (fmaxf(sqrtf(x1), EPSF) * fmaxf(sqrtf(y1), EPSF));
            *(float2*)&O[(size_t)row * H + col] = o;
        }
    }
}

// ---------------------------------------------------------------------------
extern "C" void kernel_launch(void* const* d_in, const int* in_sizes, int n_in,
                              void* d_out, int out_size) {
    const float* h1  = (const float*)d_in[0];
    const float* h2  = (const float*)d_in[1];
    const float* w_m = (const float*)d_in[2];
    float* out = (float*)d_out;

    cudaFuncSetAttribute(cmat_mma_kernel,  cudaFuncAttributeMaxDynamicSharedMemorySize, MM_SMEM);
    cudaFuncSetAttribute(apply_mma_kernel, cudaFuncAttributeMaxDynamicSharedMemorySize, MM_SMEM);
    cudaFuncSetAttribute(fm_fused_kernel,  cudaFuncAttributeMaxDynamicSharedMemorySize, FMF_SMEM);

    normalize_kernel<<<(2 * B * Nn) / 8, 256>>>(h1, h2);
    w2_prep_kernel<<<H * H / 4 / 256, 256>>>(w_m);
    cmat_mma_kernel<<<dim3(SPL2, B, 2), 256, MM_SMEM>>>();
    cmat_reduce_kernel<<<dim3(H * H / 4 / 256, B, 2), 256>>>();
    apply_mma_kernel<<<dim3(Nn / 128, B, 2), 256, MM_SMEM>>>();
    fm_fused_kernel<<<dim3(Nn / 64, B, 2), 256, FMF_SMEM>>>(h1, h2, out);
}

// round 13
// speedup vs baseline: 1.0874x; 1.0874x over previous
#include <cuda_runtime.h>
#include <cuda_bf16.h>
#include <cstdint>

#define EPSF 1e-8f
constexpr int B  = 8;
constexpr int Nn = 2048;
constexpr int H  = 128;
constexpr int LD = 132;         // padded smem leading dim (floats) for fp32 kernels
constexpr int SPL = 32;         // split-K factor for C = N^T H
constexpr int RC  = Nn / SPL;   // 64 rows per split

// Scratch (device globals: allocation-free rule)
__device__ float g_n1[B * Nn * H];
__device__ float g_n2[B * Nn * H];
__device__ float g_agg1[B * Nn * H];
__device__ float g_agg2[B * Nn * H];
__device__ float g_part[2 * B * SPL * H * H];
// bf16 split planes of normalized n: [which][b][n][k]
__device__ __nv_bfloat16 g_nbhi[2 * B * Nn * H];
__device__ __nv_bfloat16 g_nblo[2 * B * Nn * H];
// transposed split planes of C: [w][b][h][k] = C[k][h]
__device__ __nv_bfloat16 g_Cthi[2 * B * H * H];
__device__ __nv_bfloat16 g_Ctlo[2 * B * H * H];
__device__ __nv_bfloat16 g_w2hi[H * H];
__device__ __nv_bfloat16 g_w2lo[H * H];

// ======================= warp MMA helpers (base ISA, sm_80+) =================
__device__ __forceinline__ uint32_t smem_to_u32(const void* p) {
    uint32_t a;
    asm("{ .reg .u64 t; cvta.to.shared.u64 t, %1; cvt.u32.u64 %0, t; }" : "=r"(a) : "l"(p));
    return a;
}
__device__ __forceinline__ void ldsm4(uint32_t* r, uint32_t addr) {
    asm volatile("ldmatrix.sync.aligned.m8n8.x4.shared.b16 {%0,%1,%2,%3}, [%4];"
                 : "=r"(r[0]), "=r"(r[1]), "=r"(r[2]), "=r"(r[3]) : "r"(addr));
}
__device__ __forceinline__ void mma_bf16(float* c, const uint32_t* a,
                                         uint32_t b0, uint32_t b1) {
    asm volatile("mma.sync.aligned.m16n8k16.row.col.f32.bf16.bf16.f32 "
                 "{%0,%1,%2,%3}, {%4,%5,%6,%7}, {%8,%9}, {%0,%1,%2,%3};"
                 : "+f"(c[0]), "+f"(c[1]), "+f"(c[2]), "+f"(c[3])
                 : "r"(a[0]), "r"(a[1]), "r"(a[2]), "r"(a[3]), "r"(b0), "r"(b1));
}
__device__ __forceinline__ uint32_t pack_bf2(float a, float b) {
    __nv_bfloat162 t = __floats2bfloat162_rn(a, b);
    return *reinterpret_cast<uint32_t*>(&t);
}
__device__ __forceinline__ void split4(const float* v, uint2& phi, uint2& plo) {
    float hi[4], lo[4];
#pragma unroll
    for (int i = 0; i < 4; i++) {
        __nv_bfloat16 h = __float2bfloat16(v[i]);
        hi[i] = __bfloat162float(h);
        lo[i] = v[i] - hi[i];
    }
    phi = make_uint2(pack_bf2(hi[0], hi[1]), pack_bf2(hi[2], hi[3]));
    plo = make_uint2(pack_bf2(lo[0], lo[1]), pack_bf2(lo[2], lo[3]));
}

constexpr int AROW  = 272;                 // 136 bf16 per smem row
constexpr int PLANE = 128 * AROW;          // 34816 bytes
constexpr int APM_SMEM = 4 * PLANE;        // 139264

// ---------------------------------------------------------------------------
// K1: row-normalize -> fp32 n (for cmat) + bf16 hi/lo planes (for apply MMA)
// ---------------------------------------------------------------------------
__global__ void normalize_kernel(const float* __restrict__ h1,
                                 const float* __restrict__ h2) {
    int warp = (blockIdx.x * blockDim.x + threadIdx.x) >> 5;
    int lane = threadIdx.x & 31;
    int which = (warp < B * Nn) ? 0 : 1;
    int row = warp - which * B * Nn;
    const float* src = which ? h2 : h1;
    float* dst = which ? g_n2 : g_n1;

    float4 v = ((const float4*)(src + (size_t)row * H))[lane];
    float ss = v.x * v.x + v.y * v.y + v.z * v.z + v.w * v.w;
#pragma unroll
    for (int o = 16; o; o >>= 1) ss += __shfl_xor_sync(0xffffffffu, ss, o);
    float inv = 1.0f / fmaxf(sqrtf(ss), EPSF);
    float r4[4] = {v.x * inv, v.y * inv, v.z * inv, v.w * inv};
    ((float4*)(dst + (size_t)row * H))[lane] = make_float4(r4[0], r4[1], r4[2], r4[3]);

    uint2 phi, plo;
    split4(r4, phi, plo);
    size_t off = ((size_t)which * B * Nn + row) * H + lane * 4;
    *(uint2*)&g_nbhi[off] = phi;
    *(uint2*)&g_nblo[off] = plo;
}

// ---------------------------------------------------------------------------
// K2a: split-K partials of C = N^T H (fp32), RC=64 rows/CTA, 2 CTAs/SM
// ---------------------------------------------------------------------------
__global__ void __launch_bounds__(256, 2)
cmat_partial_kernel(const float* __restrict__ h1, const float* __restrict__ h2) {
    extern __shared__ float sm[];
    float* Ns = sm;                 // RC x LD
    float* Hs = sm + RC * LD;       // RC x LD
    const int s = blockIdx.x, b = blockIdx.y, w = blockIdx.z;
    const int tid = threadIdx.x;
    const float* Nsrc = (w == 0 ? g_n2 : g_n1) + (size_t)(b * Nn + s * RC) * H;
    const float* Hsrc = (w == 0 ? h2   : h1  ) + (size_t)(b * Nn + s * RC) * H;
    for (int i = tid; i < RC * (H / 4); i += 256) {
        int r = i >> 5, c4 = (i & 31) << 2;
        *(float4*)&Ns[r * LD + c4] = *(const float4*)&Nsrc[r * H + c4];
        *(float4*)&Hs[r * LD + c4] = *(const float4*)&Hsrc[r * H + c4];
    }
    __syncthreads();
    const int ty = tid >> 4, tx = tid & 15;
    const int k0 = ty * 8, h0 = tx * 8;
    float acc[8][8];
#pragma unroll
    for (int i = 0; i < 8; i++)
#pragma unroll
        for (int j = 0; j < 8; j++) acc[i][j] = 0.0f;
#pragma unroll 4
    for (int r = 0; r < RC; ++r) {
        float a[8], bb[8];
        *(float4*)&a[0]  = *(float4*)&Ns[r * LD + k0];
        *(float4*)&a[4]  = *(float4*)&Ns[r * LD + k0 + 4];
        *(float4*)&bb[0] = *(float4*)&Hs[r * LD + h0];
        *(float4*)&bb[4] = *(float4*)&Hs[r * LD + h0 + 4];
#pragma unroll
        for (int i = 0; i < 8; i++)
#pragma unroll
            for (int j = 0; j < 8; j++) acc[i][j] += a[i] * bb[j];
    }
    float* P = g_part + ((size_t)(w * B + b) * SPL + s) * (H * H);
#pragma unroll
    for (int i = 0; i < 8; i++) {
        *(float4*)&P[(k0 + i) * H + h0]     = make_float4(acc[i][0], acc[i][1], acc[i][2], acc[i][3]);
        *(float4*)&P[(k0 + i) * H + h0 + 4] = make_float4(acc[i][4], acc[i][5], acc[i][6], acc[i][7]);
    }
}

// ---------------------------------------------------------------------------
// K2b: reduce SPL partials + transpose via smem -> coalesced Ct split planes
// Block: 64x64 (k,h) tile. grid.x = 4 tiles (2x2), (b, w) on y/z.
// ---------------------------------------------------------------------------
__global__ void cmat_reduce_kernel() {
    __shared__ float t[64][65];
    const int b = blockIdx.y, w = blockIdx.z;
    const int k0 = (blockIdx.x >> 1) * 64, h0 = (blockIdx.x & 1) * 64;
    const int tid = threadIdx.x;
    const float* P = g_part + (size_t)(w * B + b) * SPL * (H * H);

    // load+sum: 64 k-rows x 16 float4 (64 h) = 1024 units, 4 per thread
#pragma unroll
    for (int j = 0; j < 4; j++) {
        int idx = tid + j * 256;
        int kr = idx >> 4, hq = (idx & 15) << 2;        // hq: 0..60
        size_t e = (size_t)(k0 + kr) * H + h0 + hq;
        float4 sum = make_float4(0.f, 0.f, 0.f, 0.f);
#pragma unroll
        for (int sp = 0; sp < SPL; sp++) {
            float4 v = *(const float4*)&P[(size_t)sp * (H * H) + e];
            sum.x += v.x; sum.y += v.y; sum.z += v.z; sum.w += v.w;
        }
        t[kr][hq] = sum.x; t[kr][hq + 1] = sum.y;
        t[kr][hq + 2] = sum.z; t[kr][hq + 3] = sum.w;
    }
    __syncthreads();

    // transpose write: Ct[h][k] = t[k][h]; coalesced uint2 (4 bf16) stores
    size_t base = (size_t)(w * B + b) * (H * H);
#pragma unroll
    for (int j = 0; j < 4; j++) {
        int idx = tid + j * 256;
        int hr = idx >> 4, kq = (idx & 15) << 2;
        float v4[4] = {t[kq][hr], t[kq + 1][hr], t[kq + 2][hr], t[kq + 3][hr]};
        uint2 phi, plo;
        split4(v4, phi, plo);
        size_t off = base + (size_t)(h0 + hr) * H + k0 + kq;
        *(uint2*)&g_Cthi[off] = phi;
        *(uint2*)&g_Ctlo[off] = plo;
    }
}

// ---------------------------------------------------------------------------
// K3: apply via mma.sync — agg[r,h] = sum_k N[r,k] * Ct[h,k], split-bf16 3-term
// ---------------------------------------------------------------------------
__global__ void __launch_bounds__(256, 1) apply_mma_kernel() {
    extern __shared__ char smem[];
    uint32_t sb = smem_to_u32(smem);
    const int tid = threadIdx.x, wid = tid >> 5, lane = tid & 31;
    const int mt = blockIdx.x, b = blockIdx.y, dir = blockIdx.z;

    size_t abase = ((size_t)dir * B * Nn + (size_t)b * Nn + (size_t)mt * 128) * H;
    const __nv_bfloat16* Ahg = g_nbhi + abase;
    const __nv_bfloat16* Alg = g_nblo + abase;
    const __nv_bfloat16* Bhg = g_Cthi + (size_t)(dir * B + b) * (H * H);
    const __nv_bfloat16* Blg = g_Ctlo + (size_t)(dir * B + b) * (H * H);

    for (int i = tid; i < 128 * 16; i += 256) {
        int r = i >> 4, ck = i & 15;
        uint32_t d = (uint32_t)r * AROW + (uint32_t)ck * 16;
        *(uint4*)(smem + d)             = *(const uint4*)(Ahg + r * H + ck * 8);
        *(uint4*)(smem + PLANE + d)     = *(const uint4*)(Alg + r * H + ck * 8);
        *(uint4*)(smem + 2 * PLANE + d) = *(const uint4*)(Bhg + r * H + ck * 8);
        *(uint4*)(smem + 3 * PLANE + d) = *(const uint4*)(Blg + r * H + ck * 8);
    }
    __syncthreads();

    const int wm = (wid >> 1) * 32, wn = (wid & 1) * 64;
    const int lr = lane & 15;
    const uint32_t lc2 = (uint32_t)(lane >> 4) * 16;
    uint32_t aoff[2], boff[4];
#pragma unroll
    for (int mi = 0; mi < 2; mi++)
        aoff[mi] = sb + (uint32_t)(wm + mi * 16 + lr) * AROW + lc2;
#pragma unroll
    for (int jp = 0; jp < 4; jp++)
        boff[jp] = sb + 2 * PLANE + (uint32_t)(wn + jp * 16 + lr) * AROW + lc2;

    float acc[2][8][4];
#pragma unroll
    for (int mi = 0; mi < 2; mi++)
#pragma unroll
        for (int j = 0; j < 8; j++)
#pragma unroll
            for (int q = 0; q < 4; q++) acc[mi][j][q] = 0.0f;

#pragma unroll 2
    for (int ks = 0; ks < 8; ks++) {
        uint32_t kb = (uint32_t)ks * 32;
        uint32_t ah[2][4], al[2][4];
#pragma unroll
        for (int mi = 0; mi < 2; mi++) {
            ldsm4(ah[mi], aoff[mi] + kb);
            ldsm4(al[mi], aoff[mi] + PLANE + kb);
        }
        uint32_t bh[4][4], bl[4][4];
#pragma unroll
        for (int jp = 0; jp < 4; jp++) {
            ldsm4(bh[jp], boff[jp] + kb);
            ldsm4(bl[jp], boff[jp] + PLANE + kb);
        }
#pragma unroll
        for (int j = 0; j < 8; j++) {
            uint32_t b0h = bh[j >> 1][j & 1], b1h = bh[j >> 1][(j & 1) + 2];
            uint32_t b0l = bl[j >> 1][j & 1], b1l = bl[j >> 1][(j & 1) + 2];
#pragma unroll
            for (int mi = 0; mi < 2; mi++) {
                mma_bf16(acc[mi][j], ah[mi], b0h, b1h);
                mma_bf16(acc[mi][j], al[mi], b0h, b1h);
                mma_bf16(acc[mi][j], ah[mi], b0l, b1l);
            }
        }
    }

    float* D = (dir == 0 ? g_agg1 : g_agg2) + ((size_t)b * Nn + (size_t)mt * 128) * H;
    const int g = lane >> 2, tc = (lane & 3) * 2;
#pragma unroll
    for (int mi = 0; mi < 2; mi++)
#pragma unroll
        for (int j = 0; j < 8; j++) {
            int row = wm + mi * 16 + g, col = wn + j * 8 + tc;
            *(float2*)&D[(size_t)row * H + col]       = make_float2(acc[mi][j][0], acc[mi][j][1]);
            *(float2*)&D[(size_t)(row + 8) * H + col] = make_float2(acc[mi][j][2], acc[mi][j][3]);
        }
}

// ---------------------------------------------------------------------------
// K4a: W2 = w*w, split to bf16 hi/lo
// ---------------------------------------------------------------------------
__global__ void w2_prep_kernel(const float* __restrict__ w_m) {
    int u = blockIdx.x * 256 + threadIdx.x;
    float4 w = *(const float4*)&w_m[u * 4];
    float v[4] = {w.x * w.x, w.y * w.y, w.z * w.z, w.w * w.w};
    uint2 phi, plo;
    split4(v, phi, plo);
    *(uint2*)&g_w2hi[u * 4] = phi;
    *(uint2*)&g_w2lo[u * 4] = plo;
}

// ---------------------------------------------------------------------------
// K4b: fused fm (round-9 winner, unchanged)
// ---------------------------------------------------------------------------
constexpr int APL      = 64 * AROW;            // 17408
constexpr int FMF_BOFF = 6 * APL;              // 104448
constexpr int FMF_SMEM = FMF_BOFF + 2 * PLANE; // 174080

__global__ void __launch_bounds__(256, 1)
fm_fused_kernel(const float* __restrict__ h1, const float* __restrict__ h2,
                float* __restrict__ out) {
    extern __shared__ char smem[];
    uint32_t sb = smem_to_u32(smem);
    const int tid = threadIdx.x, wid = tid >> 5, lane = tid & 31;
    const int mt = blockIdx.x, b = blockIdx.y, dir = blockIdx.z;

    const float* X = (dir ? h2 : h1) + ((size_t)b * Nn + (size_t)mt * 64) * H;
    const float* Y = (dir ? g_agg2 : g_agg1) + ((size_t)b * Nn + (size_t)mt * 64) * H;

    for (int i = tid; i < 64 * 32; i += 256) {
        int r = i >> 5, c4 = (i & 31) << 2;
        float4 x = *(const float4*)&X[r * H + c4];
        float4 y = *(const float4*)&Y[r * H + c4];
        float ch[3][4] = {
            {x.x * y.x, x.y * y.y, x.z * y.z, x.w * y.w},
            {x.x * x.x, x.y * x.y, x.z * x.z, x.w * x.w},
            {y.x * y.x, y.y * y.y, y.z * y.z, y.w * y.w}};
        uint32_t d = (uint32_t)r * AROW + (uint32_t)c4 * 2;
#pragma unroll
        for (int c = 0; c < 3; c++) {
            uint2 phi, plo;
            split4(ch[c], phi, plo);
            *(uint2*)(smem + (c * 2 + 0) * APL + d) = phi;
            *(uint2*)(smem + (c * 2 + 1) * APL + d) = plo;
        }
    }
    for (int i = tid; i < 128 * 16; i += 256) {
        int r = i >> 4, ck = i & 15;
        uint32_t d = (uint32_t)r * AROW + (uint32_t)ck * 16;
        *(uint4*)(smem + FMF_BOFF + d)         = *(const uint4*)(g_w2hi + r * H + ck * 8);
        *(uint4*)(smem + FMF_BOFF + PLANE + d) = *(const uint4*)(g_w2lo + r * H + ck * 8);
    }
    __syncthreads();

    const int wm = (wid >> 1) * 16, wn = (wid & 1) * 64;
    const int lr = lane & 15;
    const uint32_t lc2 = (uint32_t)(lane >> 4) * 16;
    uint32_t aoff[3][2], boff[4][2];
#pragma unroll
    for (int c = 0; c < 3; c++)
#pragma unroll
        for (int hl = 0; hl < 2; hl++)
            aoff[c][hl] = sb + (uint32_t)(c * 2 + hl) * APL + (uint32_t)(wm + lr) * AROW + lc2;
#pragma unroll
    for (int jp = 0; jp < 4; jp++)
#pragma unroll
        for (int hl = 0; hl < 2; hl++)
            boff[jp][hl] = sb + FMF_BOFF + (uint32_t)hl * PLANE +
                           (uint32_t)(wn + jp * 16 + lr) * AROW + lc2;

    float acc[3][8][4];
#pragma unroll
    for (int c = 0; c < 3; c++)
#pragma unroll
        for (int j = 0; j < 8; j++)
#pragma unroll
            for (int q = 0; q < 4; q++) acc[c][j][q] = 0.0f;

    for (int ks = 0; ks < 8; ks++) {
        uint32_t kb = (uint32_t)ks * 32;
        uint32_t ah[3][4], al[3][4];
#pragma unroll
        for (int c = 0; c < 3; c++) {
            ldsm4(ah[c], aoff[c][0] + kb);
            ldsm4(al[c], aoff[c][1] + kb);
        }
        uint32_t bh[4][4], bl[4][4];
#pragma unroll
        for (int jp = 0; jp < 4; jp++) {
            ldsm4(bh[jp], boff[jp][0] + kb);
            ldsm4(bl[jp], boff[jp][1] + kb);
        }
#pragma unroll
        for (int j = 0; j < 8; j++) {
            uint32_t b0h = bh[j >> 1][j & 1], b1h = bh[j >> 1][(j & 1) + 2];
            uint32_t b0l = bl[j >> 1][j & 1], b1l = bl[j >> 1][(j & 1) + 2];
#pragma unroll
            for (int c = 0; c < 3; c++) {
                mma_bf16(acc[c][j], ah[c], b0h, b1h);
                mma_bf16(acc[c][j], al[c], b0h, b1h);
                mma_bf16(acc[c][j], ah[c], b0l, b1l);
            }
        }
    }

    float* O = out + ((size_t)(dir * B + b) * Nn + (size_t)mt * 64) * H;
    const int g = lane >> 2, tc = (lane & 3) * 2;
#pragma unroll
    for (int j = 0; j < 8; j++) {
        int col = wn + j * 8 + tc;
#pragma unroll
        for (int half = 0; half < 2; half++) {
            int row = wm + half * 8 + g;
            float n0 = acc[0][j][half * 2], n1 = acc[0][j][half * 2 + 1];
            float x0 = acc[1][j][half * 2], x1 = acc[1][j][half * 2 + 1];
            float y0 = acc[2][j][half * 2], y1 = acc[2][j][half * 2 + 1];
            float2 o;
            o.x = n0 / (fmaxf(sqrtf(x0), EPSF) * fmaxf(sqrtf(y0), EPSF));
            o.y = n1 / (fmaxf(sqrtf(x1), EPSF) * fmaxf(sqrtf(y1), EPSF));
            *(float2*)&O[(size_t)row * H + col] = o;
        }
    }
}

// ---------------------------------------------------------------------------
extern "C" void kernel_launch(void* const* d_in, const int* in_sizes, int n_in,
                              void* d_out, int out_size) {
    const float* h1  = (const float*)d_in[0];
    const float* h2  = (const float*)d_in[1];
    const float* w_m = (const float*)d_in[2];
    float* out = (float*)d_out;

    constexpr int CM_SMEM = 2 * RC * LD * (int)sizeof(float);       // 67.6 KB

    cudaFuncSetAttribute(cmat_partial_kernel, cudaFuncAttributeMaxDynamicSharedMemorySize, CM_SMEM);
    cudaFuncSetAttribute(apply_mma_kernel,    cudaFuncAttributeMaxDynamicSharedMemorySize, APM_SMEM);
    cudaFuncSetAttribute(fm_fused_kernel,     cudaFuncAttributeMaxDynamicSharedMemorySize, FMF_SMEM);

    normalize_kernel<<<(2 * B * Nn) / 8, 256>>>(h1, h2);
    w2_prep_kernel<<<H * H / 4 / 256, 256>>>(w_m);
    cmat_partial_kernel<<<dim3(SPL, B, 2), 256, CM_SMEM>>>(h1, h2);
    cmat_reduce_kernel<<<dim3(4, B, 2), 256>>>();
    apply_mma_kernel<<<dim3(Nn / 128, B, 2), 256, APM_SMEM>>>();
    fm_fused_kernel<<<dim3(Nn / 64, B, 2), 256, FMF_SMEM>>>(h1, h2, out);
}

// round 14
// speedup vs baseline: 1.1848x; 1.0896x over previous
#include <cuda_runtime.h>
#include <cuda_bf16.h>
#include <cstdint>

#define EPSF 1e-8f
constexpr int B  = 8;
constexpr int Nn = 2048;
constexpr int H  = 128;
constexpr int LD = 132;         // padded smem leading dim (floats) for fp32 kernels
constexpr int SPL = 16;         // split-K factor for C = N^T H
constexpr int RC  = Nn / SPL;   // 128 rows per split (2 smem stages of 64)

// Scratch (device globals: allocation-free rule)
__device__ float g_n1[B * Nn * H];
__device__ float g_n2[B * Nn * H];
__device__ float g_agg1[B * Nn * H];
__device__ float g_agg2[B * Nn * H];
__device__ float g_part[2 * B * SPL * H * H];
// bf16 split planes of normalized n: [which][b][n][k]
__device__ __nv_bfloat16 g_nbhi[2 * B * Nn * H];
__device__ __nv_bfloat16 g_nblo[2 * B * Nn * H];
// transposed split planes of C: [w][b][h][k] = C[k][h]
__device__ __nv_bfloat16 g_Cthi[2 * B * H * H];
__device__ __nv_bfloat16 g_Ctlo[2 * B * H * H];
__device__ __nv_bfloat16 g_w2hi[H * H];
__device__ __nv_bfloat16 g_w2lo[H * H];

// ======================= warp MMA helpers (base ISA, sm_80+) =================
__device__ __forceinline__ uint32_t smem_to_u32(const void* p) {
    uint32_t a;
    asm("{ .reg .u64 t; cvta.to.shared.u64 t, %1; cvt.u32.u64 %0, t; }" : "=r"(a) : "l"(p));
    return a;
}
__device__ __forceinline__ void ldsm4(uint32_t* r, uint32_t addr) {
    asm volatile("ldmatrix.sync.aligned.m8n8.x4.shared.b16 {%0,%1,%2,%3}, [%4];"
                 : "=r"(r[0]), "=r"(r[1]), "=r"(r[2]), "=r"(r[3]) : "r"(addr));
}
__device__ __forceinline__ void mma_bf16(float* c, const uint32_t* a,
                                         uint32_t b0, uint32_t b1) {
    asm volatile("mma.sync.aligned.m16n8k16.row.col.f32.bf16.bf16.f32 "
                 "{%0,%1,%2,%3}, {%4,%5,%6,%7}, {%8,%9}, {%0,%1,%2,%3};"
                 : "+f"(c[0]), "+f"(c[1]), "+f"(c[2]), "+f"(c[3])
                 : "r"(a[0]), "r"(a[1]), "r"(a[2]), "r"(a[3]), "r"(b0), "r"(b1));
}
__device__ __forceinline__ uint32_t pack_bf2(float a, float b) {
    __nv_bfloat162 t = __floats2bfloat162_rn(a, b);
    return *reinterpret_cast<uint32_t*>(&t);
}
__device__ __forceinline__ void split4(const float* v, uint2& phi, uint2& plo) {
    float hi[4], lo[4];
#pragma unroll
    for (int i = 0; i < 4; i++) {
        __nv_bfloat16 h = __float2bfloat16(v[i]);
        hi[i] = __bfloat162float(h);
        lo[i] = v[i] - hi[i];
    }
    phi = make_uint2(pack_bf2(hi[0], hi[1]), pack_bf2(hi[2], hi[3]));
    plo = make_uint2(pack_bf2(lo[0], lo[1]), pack_bf2(lo[2], lo[3]));
}

constexpr int AROW  = 272;                 // 136 bf16 per smem row
constexpr int PLANE = 128 * AROW;          // 34816 bytes
constexpr int APM_SMEM = 4 * PLANE;        // 139264

// ---------------------------------------------------------------------------
// K1: row-normalize -> fp32 n (for cmat) + bf16 hi/lo planes (for apply MMA)
// ---------------------------------------------------------------------------
__global__ void normalize_kernel(const float* __restrict__ h1,
                                 const float* __restrict__ h2) {
    int warp = (blockIdx.x * blockDim.x + threadIdx.x) >> 5;
    int lane = threadIdx.x & 31;
    int which = (warp < B * Nn) ? 0 : 1;
    int row = warp - which * B * Nn;
    const float* src = which ? h2 : h1;
    float* dst = which ? g_n2 : g_n1;

    float4 v = ((const float4*)(src + (size_t)row * H))[lane];
    float ss = v.x * v.x + v.y * v.y + v.z * v.z + v.w * v.w;
#pragma unroll
    for (int o = 16; o; o >>= 1) ss += __shfl_xor_sync(0xffffffffu, ss, o);
    float inv = 1.0f / fmaxf(sqrtf(ss), EPSF);
    float r4[4] = {v.x * inv, v.y * inv, v.z * inv, v.w * inv};
    ((float4*)(dst + (size_t)row * H))[lane] = make_float4(r4[0], r4[1], r4[2], r4[3]);

    uint2 phi, plo;
    split4(r4, phi, plo);
    size_t off = ((size_t)which * B * Nn + row) * H + lane * 4;
    *(uint2*)&g_nbhi[off] = phi;
    *(uint2*)&g_nblo[off] = plo;
}

// ---------------------------------------------------------------------------
// K2a: split-K partials of C = N^T H (fp32).
// RC=128 contraction rows per CTA, staged as 2 x 64 rows in smem -> 67.6 KB,
// 2 CTAs/SM. SPL=16 keeps g_part traffic at 16 MB.
// ---------------------------------------------------------------------------
__global__ void __launch_bounds__(256, 2)
cmat_partial_kernel(const float* __restrict__ h1, const float* __restrict__ h2) {
    extern __shared__ float sm[];
    float* Ns = sm;                 // 64 x LD
    float* Hs = sm + 64 * LD;       // 64 x LD
    const int s = blockIdx.x, b = blockIdx.y, w = blockIdx.z;
    const int tid = threadIdx.x;
    const float* Nsrc = (w == 0 ? g_n2 : g_n1) + (size_t)(b * Nn + s * RC) * H;
    const float* Hsrc = (w == 0 ? h2   : h1  ) + (size_t)(b * Nn + s * RC) * H;

    const int ty = tid >> 4, tx = tid & 15;
    const int k0 = ty * 8, h0 = tx * 8;
    float acc[8][8];
#pragma unroll
    for (int i = 0; i < 8; i++)
#pragma unroll
        for (int j = 0; j < 8; j++) acc[i][j] = 0.0f;

    for (int stage = 0; stage < 2; ++stage) {
        __syncthreads();
        const float* Np = Nsrc + (size_t)stage * 64 * H;
        const float* Hp = Hsrc + (size_t)stage * 64 * H;
        for (int i = tid; i < 64 * (H / 4); i += 256) {
            int r = i >> 5, c4 = (i & 31) << 2;
            *(float4*)&Ns[r * LD + c4] = *(const float4*)&Np[r * H + c4];
            *(float4*)&Hs[r * LD + c4] = *(const float4*)&Hp[r * H + c4];
        }
        __syncthreads();

#pragma unroll 4
        for (int r = 0; r < 64; ++r) {
            float a[8], bb[8];
            *(float4*)&a[0]  = *(float4*)&Ns[r * LD + k0];
            *(float4*)&a[4]  = *(float4*)&Ns[r * LD + k0 + 4];
            *(float4*)&bb[0] = *(float4*)&Hs[r * LD + h0];
            *(float4*)&bb[4] = *(float4*)&Hs[r * LD + h0 + 4];
#pragma unroll
            for (int i = 0; i < 8; i++)
#pragma unroll
                for (int j = 0; j < 8; j++) acc[i][j] += a[i] * bb[j];
        }
    }

    float* P = g_part + ((size_t)(w * B + b) * SPL + s) * (H * H);
#pragma unroll
    for (int i = 0; i < 8; i++) {
        *(float4*)&P[(k0 + i) * H + h0]     = make_float4(acc[i][0], acc[i][1], acc[i][2], acc[i][3]);
        *(float4*)&P[(k0 + i) * H + h0 + 4] = make_float4(acc[i][4], acc[i][5], acc[i][6], acc[i][7]);
    }
}

// ---------------------------------------------------------------------------
// K2b: reduce SPL partials + transpose via smem -> coalesced Ct split planes.
// Tile 32(k) x 64(h); grid.x = 8 tiles -> 256 CTAs total.
// ---------------------------------------------------------------------------
__global__ void cmat_reduce_kernel() {
    __shared__ float t[32][65];
    const int b = blockIdx.y, w = blockIdx.z;
    const int k0 = (blockIdx.x >> 1) * 32, h0 = (blockIdx.x & 1) * 64;
    const int tid = threadIdx.x;
    const float* P = g_part + (size_t)(w * B + b) * SPL * (H * H);

    // load+sum: 32 k-rows x 16 float4 (64 h) = 512 units, 2 per thread
#pragma unroll
    for (int j = 0; j < 2; j++) {
        int idx = tid + j * 256;
        int kr = idx >> 4, hq = (idx & 15) << 2;
        size_t e = (size_t)(k0 + kr) * H + h0 + hq;
        float4 sum = make_float4(0.f, 0.f, 0.f, 0.f);
#pragma unroll
        for (int sp = 0; sp < SPL; sp++) {
            float4 v = *(const float4*)&P[(size_t)sp * (H * H) + e];
            sum.x += v.x; sum.y += v.y; sum.z += v.z; sum.w += v.w;
        }
        t[kr][hq] = sum.x; t[kr][hq + 1] = sum.y;
        t[kr][hq + 2] = sum.z; t[kr][hq + 3] = sum.w;
    }
    __syncthreads();

    // transpose write: Ct[h][k] = t[k][h]; 64 h-rows x 8 uint2 (32 k) = 512 units
    size_t base = (size_t)(w * B + b) * (H * H);
#pragma unroll
    for (int j = 0; j < 2; j++) {
        int idx = tid + j * 256;
        int hr = idx >> 3, kq = (idx & 7) << 2;
        float v4[4] = {t[kq][hr], t[kq + 1][hr], t[kq + 2][hr], t[kq + 3][hr]};
        uint2 phi, plo;
        split4(v4, phi, plo);
        size_t off = base + (size_t)(h0 + hr) * H + k0 + kq;
        *(uint2*)&g_Cthi[off] = phi;
        *(uint2*)&g_Ctlo[off] = plo;
    }
}

// ---------------------------------------------------------------------------
// K3: apply via mma.sync — agg[r,h] = sum_k N[r,k] * Ct[h,k], split-bf16 3-term
// ---------------------------------------------------------------------------
__global__ void __launch_bounds__(256, 1) apply_mma_kernel() {
    extern __shared__ char smem[];
    uint32_t sb = smem_to_u32(smem);
    const int tid = threadIdx.x, wid = tid >> 5, lane = tid & 31;
    const int mt = blockIdx.x, b = blockIdx.y, dir = blockIdx.z;

    size_t abase = ((size_t)dir * B * Nn + (size_t)b * Nn + (size_t)mt * 128) * H;
    const __nv_bfloat16* Ahg = g_nbhi + abase;
    const __nv_bfloat16* Alg = g_nblo + abase;
    const __nv_bfloat16* Bhg = g_Cthi + (size_t)(dir * B + b) * (H * H);
    const __nv_bfloat16* Blg = g_Ctlo + (size_t)(dir * B + b) * (H * H);

    for (int i = tid; i < 128 * 16; i += 256) {
        int r = i >> 4, ck = i & 15;
        uint32_t d = (uint32_t)r * AROW + (uint32_t)ck * 16;
        *(uint4*)(smem + d)             = *(const uint4*)(Ahg + r * H + ck * 8);
        *(uint4*)(smem + PLANE + d)     = *(const uint4*)(Alg + r * H + ck * 8);
        *(uint4*)(smem + 2 * PLANE + d) = *(const uint4*)(Bhg + r * H + ck * 8);
        *(uint4*)(smem + 3 * PLANE + d) = *(const uint4*)(Blg + r * H + ck * 8);
    }
    __syncthreads();

    const int wm = (wid >> 1) * 32, wn = (wid & 1) * 64;
    const int lr = lane & 15;
    const uint32_t lc2 = (uint32_t)(lane >> 4) * 16;
    uint32_t aoff[2], boff[4];
#pragma unroll
    for (int mi = 0; mi < 2; mi++)
        aoff[mi] = sb + (uint32_t)(wm + mi * 16 + lr) * AROW + lc2;
#pragma unroll
    for (int jp = 0; jp < 4; jp++)
        boff[jp] = sb + 2 * PLANE + (uint32_t)(wn + jp * 16 + lr) * AROW + lc2;

    float acc[2][8][4];
#pragma unroll
    for (int mi = 0; mi < 2; mi++)
#pragma unroll
        for (int j = 0; j < 8; j++)
#pragma unroll
            for (int q = 0; q < 4; q++) acc[mi][j][q] = 0.0f;

#pragma unroll 2
    for (int ks = 0; ks < 8; ks++) {
        uint32_t kb = (uint32_t)ks * 32;
        uint32_t ah[2][4], al[2][4];
#pragma unroll
        for (int mi = 0; mi < 2; mi++) {
            ldsm4(ah[mi], aoff[mi] + kb);
            ldsm4(al[mi], aoff[mi] + PLANE + kb);
        }
        uint32_t bh[4][4], bl[4][4];
#pragma unroll
        for (int jp = 0; jp < 4; jp++) {
            ldsm4(bh[jp], boff[jp] + kb);
            ldsm4(bl[jp], boff[jp] + PLANE + kb);
        }
#pragma unroll
        for (int j = 0; j < 8; j++) {
            uint32_t b0h = bh[j >> 1][j & 1], b1h = bh[j >> 1][(j & 1) + 2];
            uint32_t b0l = bl[j >> 1][j & 1], b1l = bl[j >> 1][(j & 1) + 2];
#pragma unroll
            for (int mi = 0; mi < 2; mi++) {
                mma_bf16(acc[mi][j], ah[mi], b0h, b1h);
                mma_bf16(acc[mi][j], al[mi], b0h, b1h);
                mma_bf16(acc[mi][j], ah[mi], b0l, b1l);
            }
        }
    }

    float* D = (dir == 0 ? g_agg1 : g_agg2) + ((size_t)b * Nn + (size_t)mt * 128) * H;
    const int g = lane >> 2, tc = (lane & 3) * 2;
#pragma unroll
    for (int mi = 0; mi < 2; mi++)
#pragma unroll
        for (int j = 0; j < 8; j++) {
            int row = wm + mi * 16 + g, col = wn + j * 8 + tc;
            *(float2*)&D[(size_t)row * H + col]       = make_float2(acc[mi][j][0], acc[mi][j][1]);
            *(float2*)&D[(size_t)(row + 8) * H + col] = make_float2(acc[mi][j][2], acc[mi][j][3]);
        }
}

// ---------------------------------------------------------------------------
// K4a: W2 = w*w, split to bf16 hi/lo
// ---------------------------------------------------------------------------
__global__ void w2_prep_kernel(const float* __restrict__ w_m) {
    int u = blockIdx.x * 256 + threadIdx.x;
    float4 w = *(const float4*)&w_m[u * 4];
    float v[4] = {w.x * w.x, w.y * w.y, w.z * w.z, w.w * w.w};
    uint2 phi, plo;
    split4(v, phi, plo);
    *(uint2*)&g_w2hi[u * 4] = phi;
    *(uint2*)&g_w2lo[u * 4] = plo;
}

// ---------------------------------------------------------------------------
// K4b: fused fm (round-9 winner, unchanged)
// ---------------------------------------------------------------------------
constexpr int APL      = 64 * AROW;            // 17408
constexpr int FMF_BOFF = 6 * APL;              // 104448
constexpr int FMF_SMEM = FMF_BOFF + 2 * PLANE; // 174080

__global__ void __launch_bounds__(256, 1)
fm_fused_kernel(const float* __restrict__ h1, const float* __restrict__ h2,
                float* __restrict__ out) {
    extern __shared__ char smem[];
    uint32_t sb = smem_to_u32(smem);
    const int tid = threadIdx.x, wid = tid >> 5, lane = tid & 31;
    const int mt = blockIdx.x, b = blockIdx.y, dir = blockIdx.z;

    const float* X = (dir ? h2 : h1) + ((size_t)b * Nn + (size_t)mt * 64) * H;
    const float* Y = (dir ? g_agg2 : g_agg1) + ((size_t)b * Nn + (size_t)mt * 64) * H;

    for (int i = tid; i < 64 * 32; i += 256) {
        int r = i >> 5, c4 = (i & 31) << 2;
        float4 x = *(const float4*)&X[r * H + c4];
        float4 y = *(const float4*)&Y[r * H + c4];
        float ch[3][4] = {
            {x.x * y.x, x.y * y.y, x.z * y.z, x.w * y.w},
            {x.x * x.x, x.y * x.y, x.z * x.z, x.w * x.w},
            {y.x * y.x, y.y * y.y, y.z * y.z, y.w * y.w}};
        uint32_t d = (uint32_t)r * AROW + (uint32_t)c4 * 2;
#pragma unroll
        for (int c = 0; c < 3; c++) {
            uint2 phi, plo;
            split4(ch[c], phi, plo);
            *(uint2*)(smem + (c * 2 + 0) * APL + d) = phi;
            *(uint2*)(smem + (c * 2 + 1) * APL + d) = plo;
        }
    }
    for (int i = tid; i < 128 * 16; i += 256) {
        int r = i >> 4, ck = i & 15;
        uint32_t d = (uint32_t)r * AROW + (uint32_t)ck * 16;
        *(uint4*)(smem + FMF_BOFF + d)         = *(const uint4*)(g_w2hi + r * H + ck * 8);
        *(uint4*)(smem + FMF_BOFF + PLANE + d) = *(const uint4*)(g_w2lo + r * H + ck * 8);
    }
    __syncthreads();

    const int wm = (wid >> 1) * 16, wn = (wid & 1) * 64;
    const int lr = lane & 15;
    const uint32_t lc2 = (uint32_t)(lane >> 4) * 16;
    uint32_t aoff[3][2], boff[4][2];
#pragma unroll
    for (int c = 0; c < 3; c++)
#pragma unroll
        for (int hl = 0; hl < 2; hl++)
            aoff[c][hl] = sb + (uint32_t)(c * 2 + hl) * APL + (uint32_t)(wm + lr) * AROW + lc2;
#pragma unroll
    for (int jp = 0; jp < 4; jp++)
#pragma unroll
        for (int hl = 0; hl < 2; hl++)
            boff[jp][hl] = sb + FMF_BOFF + (uint32_t)hl * PLANE +
                           (uint32_t)(wn + jp * 16 + lr) * AROW + lc2;

    float acc[3][8][4];
#pragma unroll
    for (int c = 0; c < 3; c++)
#pragma unroll
        for (int j = 0; j < 8; j++)
#pragma unroll
            for (int q = 0; q < 4; q++) acc[c][j][q] = 0.0f;

    for (int ks = 0; ks < 8; ks++) {
        uint32_t kb = (uint32_t)ks * 32;
        uint32_t ah[3][4], al[3][4];
#pragma unroll
        for (int c = 0; c < 3; c++) {
            ldsm4(ah[c], aoff[c][0] + kb);
            ldsm4(al[c], aoff[c][1] + kb);
        }
        uint32_t bh[4][4], bl[4][4];
#pragma unroll
        for (int jp = 0; jp < 4; jp++) {
            ldsm4(bh[jp], boff[jp][0] + kb);
            ldsm4(bl[jp], boff[jp][1] + kb);
        }
#pragma unroll
        for (int j = 0; j < 8; j++) {
            uint32_t b0h = bh[j >> 1][j & 1], b1h = bh[j >> 1][(j & 1) + 2];
            uint32_t b0l = bl[j >> 1][j & 1], b1l = bl[j >> 1][(j & 1) + 2];
#pragma unroll
            for (int c = 0; c < 3; c++) {
                mma_bf16(acc[c][j], ah[c], b0h, b1h);
                mma_bf16(acc[c][j], al[c], b0h, b1h);
                mma_bf16(acc[c][j], ah[c], b0l, b1l);
            }
        }
    }

    float* O = out + ((size_t)(dir * B + b) * Nn + (size_t)mt * 64) * H;
    const int g = lane >> 2, tc = (lane & 3) * 2;
#pragma unroll
    for (int j = 0; j < 8; j++) {
        int col = wn + j * 8 + tc;
#pragma unroll
        for (int half = 0; half < 2; half++) {
            int row = wm + half * 8 + g;
            float n0 = acc[0][j][half * 2], n1 = acc[0][j][half * 2 + 1];
            float x0 = acc[1][j][half * 2], x1 = acc[1][j][half * 2 + 1];
            float y0 = acc[2][j][half * 2], y1 = acc[2][j][half * 2 + 1];
            float2 o;
            o.x = n0 / (fmaxf(sqrtf(x0), EPSF) * fmaxf(sqrtf(y0), EPSF));
            o.y = n1 / (fmaxf(sqrtf(x1), EPSF) * fmaxf(sqrtf(y1), EPSF));
            *(float2*)&O[(size_t)row * H + col] = o;
        }
    }
}

// ---------------------------------------------------------------------------
extern "C" void kernel_launch(void* const* d_in, const int* in_sizes, int n_in,
                              void* d_out, int out_size) {
    const float* h1  = (const float*)d_in[0];
    const float* h2  = (const float*)d_in[1];
    const float* w_m = (const float*)d_in[2];
    float* out = (float*)d_out;

    constexpr int CM_SMEM = 2 * 64 * LD * (int)sizeof(float);       // 67.6 KB

    cudaFuncSetAttribute(cmat_partial_kernel, cudaFuncAttributeMaxDynamicSharedMemorySize, CM_SMEM);
    cudaFuncSetAttribute(apply_mma_kernel,    cudaFuncAttributeMaxDynamicSharedMemorySize, APM_SMEM);
    cudaFuncSetAttribute(fm_fused_kernel,     cudaFuncAttributeMaxDynamicSharedMemorySize, FMF_SMEM);

    normalize_kernel<<<(2 * B * Nn) / 8, 256>>>(h1, h2);
    w2_prep_kernel<<<H * H / 4 / 256, 256>>>(w_m);
    cmat_partial_kernel<<<dim3(SPL, B, 2), 256, CM_SMEM>>>(h1, h2);
    cmat_reduce_kernel<<<dim3(8, B, 2), 256>>>();
    apply_mma_kernel<<<dim3(Nn / 128, B, 2), 256, APM_SMEM>>>();
    fm_fused_kernel<<<dim3(Nn / 64, B, 2), 256, FMF_SMEM>>>(h1, h2, out);
}

// round 15
// speedup vs baseline: 1.4435x; 1.2183x over previous
#include <cuda_runtime.h>
#include <cuda_bf16.h>
#include <cstdint>

#define EPSF 1e-8f
constexpr int B  = 8;
constexpr int Nn = 2048;
constexpr int H  = 128;
constexpr int SPL = 16;         // split-K factor for C = N^T H
// each cmat CTA handles 128 contraction rows as 2 stages of 64

// Scratch (device globals: allocation-free rule)
__device__ float g_agg1[B * Nn * H];
__device__ float g_agg2[B * Nn * H];
__device__ float g_part[2 * B * SPL * H * H];   // partials already in Ct [h][k] layout
// bf16 split planes of normalized n and raw h: [which][b][n][k]
__device__ __nv_bfloat16 g_nbhi[2 * B * Nn * H];
__device__ __nv_bfloat16 g_nblo[2 * B * Nn * H];
__device__ __nv_bfloat16 g_hbhi[2 * B * Nn * H];
__device__ __nv_bfloat16 g_hblo[2 * B * Nn * H];
// transposed split planes of C: [w][b][h][k] = C[k][h]
__device__ __nv_bfloat16 g_Cthi[2 * B * H * H];
__device__ __nv_bfloat16 g_Ctlo[2 * B * H * H];
__device__ __nv_bfloat16 g_w2hi[H * H];
__device__ __nv_bfloat16 g_w2lo[H * H];

// ======================= warp MMA helpers (base ISA, sm_80+) =================
__device__ __forceinline__ uint32_t smem_to_u32(const void* p) {
    uint32_t a;
    asm("{ .reg .u64 t; cvta.to.shared.u64 t, %1; cvt.u32.u64 %0, t; }" : "=r"(a) : "l"(p));
    return a;
}
__device__ __forceinline__ void ldsm4(uint32_t* r, uint32_t addr) {
    asm volatile("ldmatrix.sync.aligned.m8n8.x4.shared.b16 {%0,%1,%2,%3}, [%4];"
                 : "=r"(r[0]), "=r"(r[1]), "=r"(r[2]), "=r"(r[3]) : "r"(addr));
}
__device__ __forceinline__ void ldsm4t(uint32_t* r, uint32_t addr) {
    asm volatile("ldmatrix.sync.aligned.m8n8.x4.trans.shared.b16 {%0,%1,%2,%3}, [%4];"
                 : "=r"(r[0]), "=r"(r[1]), "=r"(r[2]), "=r"(r[3]) : "r"(addr));
}
__device__ __forceinline__ void mma_bf16(float* c, const uint32_t* a,
                                         uint32_t b0, uint32_t b1) {
    asm volatile("mma.sync.aligned.m16n8k16.row.col.f32.bf16.bf16.f32 "
                 "{%0,%1,%2,%3}, {%4,%5,%6,%7}, {%8,%9}, {%0,%1,%2,%3};"
                 : "+f"(c[0]), "+f"(c[1]), "+f"(c[2]), "+f"(c[3])
                 : "r"(a[0]), "r"(a[1]), "r"(a[2]), "r"(a[3]), "r"(b0), "r"(b1));
}
__device__ __forceinline__ uint32_t pack_bf2(float a, float b) {
    __nv_bfloat162 t = __floats2bfloat162_rn(a, b);
    return *reinterpret_cast<uint32_t*>(&t);
}
__device__ __forceinline__ void split4(const float* v, uint2& phi, uint2& plo) {
    float hi[4], lo[4];
#pragma unroll
    for (int i = 0; i < 4; i++) {
        __nv_bfloat16 h = __float2bfloat16(v[i]);
        hi[i] = __bfloat162float(h);
        lo[i] = v[i] - hi[i];
    }
    phi = make_uint2(pack_bf2(hi[0], hi[1]), pack_bf2(hi[2], hi[3]));
    plo = make_uint2(pack_bf2(lo[0], lo[1]), pack_bf2(lo[2], lo[3]));
}

constexpr int AROW  = 272;                 // 136 bf16 per smem row
constexpr int PLANE = 128 * AROW;          // 34816 bytes
constexpr int PL64  = 64 * AROW;           // 17408 bytes
constexpr int APM_SMEM = 4 * PLANE;        // 139264
constexpr int CMM_SMEM = 4 * PL64;         // 69632 -> 2 CTAs/SM

// ---------------------------------------------------------------------------
// K1: row-normalize -> bf16 hi/lo planes of n AND raw h (no fp32 n needed)
// ---------------------------------------------------------------------------
__global__ void normalize_kernel(const float* __restrict__ h1,
                                 const float* __restrict__ h2) {
    int warp = (blockIdx.x * blockDim.x + threadIdx.x) >> 5;
    int lane = threadIdx.x & 31;
    int which = (warp < B * Nn) ? 0 : 1;
    int row = warp - which * B * Nn;
    const float* src = which ? h2 : h1;

    float4 v = ((const float4*)(src + (size_t)row * H))[lane];
    float ss = v.x * v.x + v.y * v.y + v.z * v.z + v.w * v.w;
#pragma unroll
    for (int o = 16; o; o >>= 1) ss += __shfl_xor_sync(0xffffffffu, ss, o);
    float inv = 1.0f / fmaxf(sqrtf(ss), EPSF);

    size_t off = ((size_t)which * B * Nn + row) * H + lane * 4;
    float r4[4] = {v.x * inv, v.y * inv, v.z * inv, v.w * inv};
    uint2 phi, plo;
    split4(r4, phi, plo);
    *(uint2*)&g_nbhi[off] = phi;
    *(uint2*)&g_nblo[off] = plo;

    float h4[4] = {v.x, v.y, v.z, v.w};
    split4(h4, phi, plo);
    *(uint2*)&g_hbhi[off] = phi;
    *(uint2*)&g_hblo[off] = plo;
}

// ---------------------------------------------------------------------------
// K2a: Ct partials via mma.sync, trans fragments (round-10-verified mapping).
//   Ct[h,k] = sum_n H[n,h] * N[n,k]; w=0 uses which=1 (h2,n2), w=1 uses which=0.
// CTA (s,b,w): 128 contraction rows (2 stages of 64), output 128x128 in [h][k].
// smem 69.6 KB -> 2 CTAs/SM, 256 CTAs.
// ---------------------------------------------------------------------------
__global__ void __launch_bounds__(256, 2) cmat_mma_kernel() {
    extern __shared__ char smem[];
    uint32_t sb = smem_to_u32(smem);
    const int tid = threadIdx.x, wid = tid >> 5, lane = tid & 31;
    const int s = blockIdx.x, b = blockIdx.y, w = blockIdx.z;
    const int which = 1 - w;

    size_t base = ((size_t)which * B * Nn + (size_t)b * Nn + (size_t)s * 128) * H;
    const __nv_bfloat16* Hh = g_hbhi + base;
    const __nv_bfloat16* Hl = g_hblo + base;
    const __nv_bfloat16* Nh = g_nbhi + base;
    const __nv_bfloat16* Nl = g_nblo + base;

    const int wm = (wid >> 1) * 32, wn = (wid & 1) * 64;   // wm: h rows, wn: k cols
    // trans ldmatrix address components (verified round 10)
    const int cA = (lane & 7) + ((lane >> 4) << 3);        // A: contraction row
    const int mA = ((lane >> 3) & 1) * 8;                  // A: h col offset
    const int nB = (lane & 7) + ((lane >> 3) & 1) * 8;     // B: contraction row
    const int kB = (lane >> 4) * 8;                        // B: k col offset

    float acc[2][8][4];
#pragma unroll
    for (int mi = 0; mi < 2; mi++)
#pragma unroll
        for (int j = 0; j < 8; j++)
#pragma unroll
            for (int q = 0; q < 4; q++) acc[mi][j][q] = 0.0f;

    for (int stage = 0; stage < 2; ++stage) {
        __syncthreads();
        const size_t roff = (size_t)stage * 64 * H;
        for (int i = tid; i < 64 * 16; i += 256) {
            int r = i >> 4, ck = i & 15;
            uint32_t d = (uint32_t)r * AROW + (uint32_t)ck * 16;
            *(uint4*)(smem + d)            = *(const uint4*)(Hh + roff + r * H + ck * 8);
            *(uint4*)(smem + PL64 + d)     = *(const uint4*)(Hl + roff + r * H + ck * 8);
            *(uint4*)(smem + 2 * PL64 + d) = *(const uint4*)(Nh + roff + r * H + ck * 8);
            *(uint4*)(smem + 3 * PL64 + d) = *(const uint4*)(Nl + roff + r * H + ck * 8);
        }
        __syncthreads();

#pragma unroll
        for (int ks = 0; ks < 4; ks++) {
            const int c0 = ks * 16;
            uint32_t ah[2][4], al[2][4];
#pragma unroll
            for (int mi = 0; mi < 2; mi++) {
                uint32_t addr = sb + (uint32_t)(c0 + cA) * AROW +
                                (uint32_t)(wm + mi * 16 + mA) * 2;
                ldsm4t(ah[mi], addr);
                ldsm4t(al[mi], addr + PL64);
            }
            uint32_t bh[4][4], bl[4][4];
#pragma unroll
            for (int jp = 0; jp < 4; jp++) {
                uint32_t addr = sb + 2 * PL64 + (uint32_t)(c0 + nB) * AROW +
                                (uint32_t)(wn + jp * 16 + kB) * 2;
                ldsm4t(bh[jp], addr);
                ldsm4t(bl[jp], addr + PL64);
            }
#pragma unroll
            for (int j = 0; j < 8; j++) {
                uint32_t b0h = bh[j >> 1][(j & 1) * 2], b1h = bh[j >> 1][(j & 1) * 2 + 1];
                uint32_t b0l = bl[j >> 1][(j & 1) * 2], b1l = bl[j >> 1][(j & 1) * 2 + 1];
#pragma unroll
                for (int mi = 0; mi < 2; mi++) {
                    mma_bf16(acc[mi][j], ah[mi], b0h, b1h);   // hi*hi
                    mma_bf16(acc[mi][j], al[mi], b0h, b1h);   // lo*hi
                    mma_bf16(acc[mi][j], ah[mi], b0l, b1l);   // hi*lo
                }
            }
        }
    }

    // store partials directly in Ct [h][k] layout
    float* P = g_part + ((size_t)(w * B + b) * SPL + s) * (H * H);
    const int g = lane >> 2, tc = (lane & 3) * 2;
#pragma unroll
    for (int mi = 0; mi < 2; mi++)
#pragma unroll
        for (int j = 0; j < 8; j++) {
            int row = wm + mi * 16 + g, col = wn + j * 8 + tc;
            *(float2*)&P[(size_t)row * H + col]       = make_float2(acc[mi][j][0], acc[mi][j][1]);
            *(float2*)&P[(size_t)(row + 8) * H + col] = make_float2(acc[mi][j][2], acc[mi][j][3]);
        }
}

// ---------------------------------------------------------------------------
// K2b: reduce SPL partials -> Ct split planes. Pure coalesced elementwise
// (partials already in [h][k] layout). grid (16, B, 2) = 256 CTAs.
// ---------------------------------------------------------------------------
__global__ void cmat_reduce_kernel() {
    const int b = blockIdx.y, w = blockIdx.z;
    const int u = blockIdx.x * 256 + threadIdx.x;        // float4 unit, 4096 per (b,w)
    const float* P = g_part + (size_t)(w * B + b) * SPL * (H * H);
    float4 sum = make_float4(0.f, 0.f, 0.f, 0.f);
#pragma unroll
    for (int sp = 0; sp < SPL; sp++) {
        float4 v = *(const float4*)&P[(size_t)sp * (H * H) + u * 4];
        sum.x += v.x; sum.y += v.y; sum.z += v.z; sum.w += v.w;
    }
    float v4[4] = {sum.x, sum.y, sum.z, sum.w};
    uint2 phi, plo;
    split4(v4, phi, plo);
    size_t off = (size_t)(w * B + b) * (H * H) + (size_t)u * 4;
    *(uint2*)&g_Cthi[off] = phi;
    *(uint2*)&g_Ctlo[off] = plo;
}

// ---------------------------------------------------------------------------
// K3: apply via mma.sync — agg[r,h] = sum_k N[r,k] * Ct[h,k], split-bf16 3-term
// ---------------------------------------------------------------------------
__global__ void __launch_bounds__(256, 1) apply_mma_kernel() {
    extern __shared__ char smem[];
    uint32_t sb = smem_to_u32(smem);
    const int tid = threadIdx.x, wid = tid >> 5, lane = tid & 31;
    const int mt = blockIdx.x, b = blockIdx.y, dir = blockIdx.z;

    size_t abase = ((size_t)dir * B * Nn + (size_t)b * Nn + (size_t)mt * 128) * H;
    const __nv_bfloat16* Ahg = g_nbhi + abase;
    const __nv_bfloat16* Alg = g_nblo + abase;
    const __nv_bfloat16* Bhg = g_Cthi + (size_t)(dir * B + b) * (H * H);
    const __nv_bfloat16* Blg = g_Ctlo + (size_t)(dir * B + b) * (H * H);

    for (int i = tid; i < 128 * 16; i += 256) {
        int r = i >> 4, ck = i & 15;
        uint32_t d = (uint32_t)r * AROW + (uint32_t)ck * 16;
        *(uint4*)(smem + d)             = *(const uint4*)(Ahg + r * H + ck * 8);
        *(uint4*)(smem + PLANE + d)     = *(const uint4*)(Alg + r * H + ck * 8);
        *(uint4*)(smem + 2 * PLANE + d) = *(const uint4*)(Bhg + r * H + ck * 8);
        *(uint4*)(smem + 3 * PLANE + d) = *(const uint4*)(Blg + r * H + ck * 8);
    }
    __syncthreads();

    const int wm = (wid >> 1) * 32, wn = (wid & 1) * 64;
    const int lr = lane & 15;
    const uint32_t lc2 = (uint32_t)(lane >> 4) * 16;
    uint32_t aoff[2], boff[4];
#pragma unroll
    for (int mi = 0; mi < 2; mi++)
        aoff[mi] = sb + (uint32_t)(wm + mi * 16 + lr) * AROW + lc2;
#pragma unroll
    for (int jp = 0; jp < 4; jp++)
        boff[jp] = sb + 2 * PLANE + (uint32_t)(wn + jp * 16 + lr) * AROW + lc2;

    float acc[2][8][4];
#pragma unroll
    for (int mi = 0; mi < 2; mi++)
#pragma unroll
        for (int j = 0; j < 8; j++)
#pragma unroll
            for (int q = 0; q < 4; q++) acc[mi][j][q] = 0.0f;

#pragma unroll 2
    for (int ks = 0; ks < 8; ks++) {
        uint32_t kb = (uint32_t)ks * 32;
        uint32_t ah[2][4], al[2][4];
#pragma unroll
        for (int mi = 0; mi < 2; mi++) {
            ldsm4(ah[mi], aoff[mi] + kb);
            ldsm4(al[mi], aoff[mi] + PLANE + kb);
        }
        uint32_t bh[4][4], bl[4][4];
#pragma unroll
        for (int jp = 0; jp < 4; jp++) {
            ldsm4(bh[jp], boff[jp] + kb);
            ldsm4(bl[jp], boff[jp] + PLANE + kb);
        }
#pragma unroll
        for (int j = 0; j < 8; j++) {
            uint32_t b0h = bh[j >> 1][j & 1], b1h = bh[j >> 1][(j & 1) + 2];
            uint32_t b0l = bl[j >> 1][j & 1], b1l = bl[j >> 1][(j & 1) + 2];
#pragma unroll
            for (int mi = 0; mi < 2; mi++) {
                mma_bf16(acc[mi][j], ah[mi], b0h, b1h);
                mma_bf16(acc[mi][j], al[mi], b0h, b1h);
                mma_bf16(acc[mi][j], ah[mi], b0l, b1l);
            }
        }
    }

    float* D = (dir == 0 ? g_agg1 : g_agg2) + ((size_t)b * Nn + (size_t)mt * 128) * H;
    const int g = lane >> 2, tc = (lane & 3) * 2;
#pragma unroll
    for (int mi = 0; mi < 2; mi++)
#pragma unroll
        for (int j = 0; j < 8; j++) {
            int row = wm + mi * 16 + g, col = wn + j * 8 + tc;
            *(float2*)&D[(size_t)row * H + col]       = make_float2(acc[mi][j][0], acc[mi][j][1]);
            *(float2*)&D[(size_t)(row + 8) * H + col] = make_float2(acc[mi][j][2], acc[mi][j][3]);
        }
}

// ---------------------------------------------------------------------------
// K4a: W2 = w*w, split to bf16 hi/lo
// ---------------------------------------------------------------------------
__global__ void w2_prep_kernel(const float* __restrict__ w_m) {
    int u = blockIdx.x * 256 + threadIdx.x;
    float4 w = *(const float4*)&w_m[u * 4];
    float v[4] = {w.x * w.x, w.y * w.y, w.z * w.z, w.w * w.w};
    uint2 phi, plo;
    split4(v, phi, plo);
    *(uint2*)&g_w2hi[u * 4] = phi;
    *(uint2*)&g_w2lo[u * 4] = plo;
}

// ---------------------------------------------------------------------------
// K4b: fused fm (round-9 winner, unchanged)
// ---------------------------------------------------------------------------
constexpr int APL      = 64 * AROW;            // 17408
constexpr int FMF_BOFF = 6 * APL;              // 104448
constexpr int FMF_SMEM = FMF_BOFF + 2 * PLANE; // 174080

__global__ void __launch_bounds__(256, 1)
fm_fused_kernel(const float* __restrict__ h1, const float* __restrict__ h2,
                float* __restrict__ out) {
    extern __shared__ char smem[];
    uint32_t sb = smem_to_u32(smem);
    const int tid = threadIdx.x, wid = tid >> 5, lane = tid & 31;
    const int mt = blockIdx.x, b = blockIdx.y, dir = blockIdx.z;

    const float* X = (dir ? h2 : h1) + ((size_t)b * Nn + (size_t)mt * 64) * H;
    const float* Y = (dir ? g_agg2 : g_agg1) + ((size_t)b * Nn + (size_t)mt * 64) * H;

    for (int i = tid; i < 64 * 32; i += 256) {
        int r = i >> 5, c4 = (i & 31) << 2;
        float4 x = *(const float4*)&X[r * H + c4];
        float4 y = *(const float4*)&Y[r * H + c4];
        float ch[3][4] = {
            {x.x * y.x, x.y * y.y, x.z * y.z, x.w * y.w},
            {x.x * x.x, x.y * x.y, x.z * x.z, x.w * x.w},
            {y.x * y.x, y.y * y.y, y.z * y.z, y.w * y.w}};
        uint32_t d = (uint32_t)r * AROW + (uint32_t)c4 * 2;
#pragma unroll
        for (int c = 0; c < 3; c++) {
            uint2 phi, plo;
            split4(ch[c], phi, plo);
            *(uint2*)(smem + (c * 2 + 0) * APL + d) = phi;
            *(uint2*)(smem + (c * 2 + 1) * APL + d) = plo;
        }
    }
    for (int i = tid; i < 128 * 16; i += 256) {
        int r = i >> 4, ck = i & 15;
        uint32_t d = (uint32_t)r * AROW + (uint32_t)ck * 16;
        *(uint4*)(smem + FMF_BOFF + d)         = *(const uint4*)(g_w2hi + r * H + ck * 8);
        *(uint4*)(smem + FMF_BOFF + PLANE + d) = *(const uint4*)(g_w2lo + r * H + ck * 8);
    }
    __syncthreads();

    const int wm = (wid >> 1) * 16, wn = (wid & 1) * 64;
    const int lr = lane & 15;
    const uint32_t lc2 = (uint32_t)(lane >> 4) * 16;
    uint32_t aoff[3][2], boff[4][2];
#pragma unroll
    for (int c = 0; c < 3; c++)
#pragma unroll
        for (int hl = 0; hl < 2; hl++)
            aoff[c][hl] = sb + (uint32_t)(c * 2 + hl) * APL + (uint32_t)(wm + lr) * AROW + lc2;
#pragma unroll
    for (int jp = 0; jp < 4; jp++)
#pragma unroll
        for (int hl = 0; hl < 2; hl++)
            boff[jp][hl] = sb + FMF_BOFF + (uint32_t)hl * PLANE +
                           (uint32_t)(wn + jp * 16 + lr) * AROW + lc2;

    float acc[3][8][4];
#pragma unroll
    for (int c = 0; c < 3; c++)
#pragma unroll
        for (int j = 0; j < 8; j++)
#pragma unroll
            for (int q = 0; q < 4; q++) acc[c][j][q] = 0.0f;

    for (int ks = 0; ks < 8; ks++) {
        uint32_t kb = (uint32_t)ks * 32;
        uint32_t ah[3][4], al[3][4];
#pragma unroll
        for (int c = 0; c < 3; c++) {
            ldsm4(ah[c], aoff[c][0] + kb);
            ldsm4(al[c], aoff[c][1] + kb);
        }
        uint32_t bh[4][4], bl[4][4];
#pragma unroll
        for (int jp = 0; jp < 4; jp++) {
            ldsm4(bh[jp], boff[jp][0] + kb);
            ldsm4(bl[jp], boff[jp][1] + kb);
        }
#pragma unroll
        for (int j = 0; j < 8; j++) {
            uint32_t b0h = bh[j >> 1][j & 1], b1h = bh[j >> 1][(j & 1) + 2];
            uint32_t b0l = bl[j >> 1][j & 1], b1l = bl[j >> 1][(j & 1) + 2];
#pragma unroll
            for (int c = 0; c < 3; c++) {
                mma_bf16(acc[c][j], ah[c], b0h, b1h);
                mma_bf16(acc[c][j], al[c], b0h, b1h);
                mma_bf16(acc[c][j], ah[c], b0l, b1l);
            }
        }
    }

    float* O = out + ((size_t)(dir * B + b) * Nn + (size_t)mt * 64) * H;
    const int g = lane >> 2, tc = (lane & 3) * 2;
#pragma unroll
    for (int j = 0; j < 8; j++) {
        int col = wn + j * 8 + tc;
#pragma unroll
        for (int half = 0; half < 2; half++) {
            int row = wm + half * 8 + g;
            float n0 = acc[0][j][half * 2], n1 = acc[0][j][half * 2 + 1];
            float x0 = acc[1][j][half * 2], x1 = acc[1][j][half * 2 + 1];
            float y0 = acc[2][j][half * 2], y1 = acc[2][j][half * 2 + 1];
            float2 o;
            o.x = n0 / (fmaxf(sqrtf(x0), EPSF) * fmaxf(sqrtf(y0), EPSF));
            o.y = n1 / (fmaxf(sqrtf(x1), EPSF) * fmaxf(sqrtf(y1), EPSF));
            *(float2*)&O[(size_t)row * H + col] = o;
        }
    }
}

// ---------------------------------------------------------------------------
extern "C" void kernel_launch(void* const* d_in, const int* in_sizes, int n_in,
                              void* d_out, int out_size) {
    const float* h1  = (const float*)d_in[0];
    const float* h2  = (const float*)d_in[1];
    const float* w_m = (const float*)d_in[2];
    float* out = (float*)d_out;

    cudaFuncSetAttribute(cmat_mma_kernel,  cudaFuncAttributeMaxDynamicSharedMemorySize, CMM_SMEM);
    cudaFuncSetAttribute(apply_mma_kernel, cudaFuncAttributeMaxDynamicSharedMemorySize, APM_SMEM);
    cudaFuncSetAttribute(fm_fused_kernel,  cudaFuncAttributeMaxDynamicSharedMemorySize, FMF_SMEM);

    normalize_kernel<<<(2 * B * Nn) / 8, 256>>>(h1, h2);
    w2_prep_kernel<<<H * H / 4 / 256, 256>>>(w_m);
    cmat_mma_kernel<<<dim3(SPL, B, 2), 256, CMM_SMEM>>>();
    cmat_reduce_kernel<<<dim3(16, B, 2), 256>>>();
    apply_mma_kernel<<<dim3(Nn / 128, B, 2), 256, APM_SMEM>>>();
    fm_fused_kernel<<<dim3(Nn / 64, B, 2), 256, FMF_SMEM>>>(h1, h2, out);
}